// round 6
// baseline (speedup 1.0000x reference)
#include <cuda_runtime.h>
#include <math.h>

#define SR_F        48000.0f
#define SOUND_SPEED 343.0f
#define MAX_ORDER   10
#define RIR_LEN     24000
#define TAPS        81
#define HALF        40
#define AXN         42            // axis-image table size (2*(2*10+1))
#define NVALID      1561          // #(ax,ay,az) triples with tot_order <= 10 (exact)
#define MAXB        16

// ---------------------------------------------------------------------------
// Compile-time table of valid axis-index triples (tot_order <= MAX_ORDER),
// packed as ax + 42*ay + 42*42*az. Batch-independent.
// ---------------------------------------------------------------------------
constexpr int axis_order_ct(int a) {
    int p = (a >= 21) ? 1 : 0;
    int n = a - 21 * p - 10;
    int o1 = n - p; if (o1 < 0) o1 = -o1;
    int o2 = n;     if (o2 < 0) o2 = -o2;
    return o1 + o2;
}

struct ValidTable {
    int v[NVALID];
    constexpr ValidTable() : v() {
        int ord[AXN] = {};
        for (int a = 0; a < AXN; ++a) ord[a] = axis_order_ct(a);
        int s = 0;
        for (int az = 0; az < AXN; ++az)
            for (int ay = 0; ay < AXN; ++ay)
                for (int ax = 0; ax < AXN; ++ax)
                    if (ord[ax] + ord[ay] + ord[az] <= MAX_ORDER)
                        v[s++] = ax + AXN * ay + AXN * AXN * az;
    }
};

__device__ const ValidTable VT = ValidTable();

__device__ float2 g_tab[TAPS];   // {cos, sin}(pi*k/41)

__constant__ float BETA_POW[11] = {
    1.0f, 0.9f, 0.81f, 0.729f, 0.6561f, 0.59049f,
    0.531441f, 0.4782969f, 0.43046721f, 0.387420489f, 0.3486784401f
};

__device__ __forceinline__ void decode_axis(int a, float& sign, float& off, int& order)
{
    int p = (a >= 21) ? 1 : 0;
    int n = a - 21 * p - 10;
    sign  = (float)(1 - 2 * p);
    off   = (float)(2 * n);
    order = abs(n - p) + abs(n);
}

__device__ __forceinline__ float rcp_approx(float x)
{
    float r;
    asm("rcp.approx.f32 %0, %1;" : "=f"(r) : "f"(x));
    return r;
}

// Scalar tap value (head/tail path): amp*sinc(t)*win(t), t = tap-40-frac.
__device__ __forceinline__ float tapval(int tap, float frac, float amp, float c,
                                        float cw, float sw)
{
    float t = (float)(tap - HALF) - frac;
    float v;
    if (t == 0.0f) v = amp;
    else           v = __fdividef((tap & 1) ? c : -c, t);
    if (tap == 0 && frac > 0.0f) v = 0.0f;                   // |t| > HALF
    float2 cs = g_tab[tap];
    return v * (0.5f + 0.5f * fmaf(cs.x, cw, cs.y * sw));
}

// ---------------------------------------------------------------------------
// Kernel A: zero RIR (float4), tap cos/sin table, origin.
// d_out layout: [B*RIR_LEN floats rir][B floats origin]
// ---------------------------------------------------------------------------
__global__ void __launch_bounds__(256)
prep_kernel(const float* __restrict__ in, float* __restrict__ out, int B, int zeroN4)
{
    int i = blockIdx.x * blockDim.x + threadIdx.x;

    if (i < zeroN4)
        ((float4*)out)[i] = make_float4(0.f, 0.f, 0.f, 0.f);

    if (i < TAPS) {
        float a = (float)i * (1.0f / 41.0f);
        g_tab[i] = make_float2(cospif(a), sinpif(a));
    }

    if (i < B) {
        const float* row = in + i * 9;
        float rx = row[0] * 10.0f, ry = row[1] * 10.0f, rz = row[2] * 10.0f;
        float dx = (row[3] - row[6]) * rx;
        float dy = (row[4] - row[7]) * ry;
        float dz = (row[5] - row[8]) * rz;
        out[B * RIR_LEN + i] =
            40.0f + SR_F * sqrtf(dx * dx + dy * dy + dz * dz) / SOUND_SPEED;
    }
}

// ---------------------------------------------------------------------------
// Kernel B: one warp per record.
// Lane 0 builds the record (image geometry), shuffles it to the warp.
// Lanes 0..body-1: 4 taps each via ONE rcp.approx (Montgomery batch inverse)
//                  + red.global.add.v4.f32.
// Lanes 20..22: head scalars; lanes 24..26: tail scalars.
// ---------------------------------------------------------------------------
__global__ void __launch_bounds__(256)
tap_kernel(const float* __restrict__ in, float* __restrict__ out, int nrec)
{
    int w    = (blockIdx.x * blockDim.x + threadIdx.x) >> 5;
    int lane = threadIdx.x & 31;
    if (w >= nrec) return;

    int b = w / NVALID;
    int s = w - b * NVALID;
    int bofs  = b * RIR_LEN;
    int end_g = bofs + RIR_LEN;

    float frac = 0.f, amp = 0.f, c = 0.f, cw = 0.f, sw = 0.f;
    int base_g = 0;

    if (lane == 0) {
        int img = VT.v[s];
        int ax = img % AXN;
        int ay = (img / AXN) % AXN;
        int az = img / (AXN * AXN);

        float sgx, ofx; int ox; decode_axis(ax, sgx, ofx, ox);
        float sgy, ofy; int oy; decode_axis(ay, sgy, ofy, oy);
        float sgz, ofz; int oz; decode_axis(az, sgz, ofz, oz);

        const float* row = in + b * 9;
        float rx = row[0] * 10.0f, ry = row[1] * 10.0f, rz = row[2] * 10.0f;
        float mx = row[3] * rx,    my = row[4] * ry,    mz = row[5] * rz;
        float sx = row[6] * rx,    sy = row[7] * ry,    sz = row[8] * rz;

        float dx = sgx * sx + ofx * rx - mx;
        float dy = sgy * sy + ofy * ry - my;
        float dz = sgz * sz + ofz * rz - mz;

        float dist = sqrtf(dx * dx + dy * dy + dz * dz);
        float tau  = SR_F * dist / SOUND_SPEED;
        float i0   = floorf(tau);
        frac = tau - i0;

        const float INV_PI = 0.318309886183790672f;
        int base = (int)i0 + HALF;
        amp    = BETA_POW[ox + oy + oz] / (4.0f * 3.14159265358979323846f * dist);
        base_g = (base >= RIR_LEN) ? end_g : bofs + base;
        c      = amp * sinpif(frac) * INV_PI;
        float bb = (40.0f + frac) * (1.0f / 41.0f);
        cw = cospif(bb);
        sw = sinpif(bb);
    }

    const unsigned FULL = 0xFFFFFFFFu;
    base_g = __shfl_sync(FULL, base_g, 0);
    frac   = __shfl_sync(FULL, frac,   0);
    amp    = __shfl_sync(FULL, amp,    0);
    c      = __shfl_sync(FULL, c,      0);
    cw     = __shfl_sync(FULL, cw,     0);
    sw     = __shfl_sync(FULL, sw,     0);

    int len = end_g - base_g;
    if (len <= 0) return;
    if (len > TAPS) len = TAPS;

    int head = (4 - (base_g & 3)) & 3;
    if (head > len) head = len;
    int body = (len - head) >> 2;            // # of v4 chunks (<= 20)
    int tail = len - head - (body << 2);     // <= 3

    if (lane < body) {
        int tap0 = head + (lane << 2);
        float tb = (float)(tap0 - HALF) - frac;
        float t0 = tb, t1 = tb + 1.0f, t2 = tb + 2.0f, t3 = tb + 3.0f;
        bool z0 = (t0 == 0.0f), z1 = (t1 == 0.0f), z2 = (t2 == 0.0f), z3 = (t3 == 0.0f);
        float u0 = z0 ? 1.0f : t0;
        float u1 = z1 ? 1.0f : t1;
        float u2 = z2 ? 1.0f : t2;
        float u3 = z3 ? 1.0f : t3;

        // Montgomery batch inverse: one rcp for four reciprocals.
        float p01   = u0 * u1;
        float p012  = p01 * u2;
        float p0123 = p012 * u3;
        float r = rcp_approx(p0123);
        float inv3 = r * p012;  r *= u3;
        float inv2 = r * p01;   r *= u2;
        float inv1 = r * u0;
        float inv0 = r * u1;

        float c0 = (tap0 & 1) ? c : -c;      // sign alternates with tap parity
        float v0 = z0 ? amp :  c0 * inv0;
        float v1 = z1 ? amp : -c0 * inv1;
        float v2 = z2 ? amp :  c0 * inv2;
        float v3 = z3 ? amp : -c0 * inv3;
        if (tap0 == 0 && frac > 0.0f) v0 = 0.0f;   // |t| > HALF at tap 0

        float2 cs0 = g_tab[tap0 + 0];
        float2 cs1 = g_tab[tap0 + 1];
        float2 cs2 = g_tab[tap0 + 2];
        float2 cs3 = g_tab[tap0 + 3];
        v0 *= 0.5f + 0.5f * fmaf(cs0.x, cw, cs0.y * sw);
        v1 *= 0.5f + 0.5f * fmaf(cs1.x, cw, cs1.y * sw);
        v2 *= 0.5f + 0.5f * fmaf(cs2.x, cw, cs2.y * sw);
        v3 *= 0.5f + 0.5f * fmaf(cs3.x, cw, cs3.y * sw);

        float* addr = out + base_g + tap0;   // 16B aligned
        asm volatile("red.global.add.v4.f32 [%0], {%1, %2, %3, %4};"
                     :: "l"(addr), "f"(v0), "f"(v1), "f"(v2), "f"(v3)
                     : "memory");
    } else if (lane >= 20 && lane < 20 + head) {
        int tap = lane - 20;
        atomicAdd(out + base_g + tap, tapval(tap, frac, amp, c, cw, sw));
    } else if (lane >= 24 && lane < 24 + tail) {
        int tap = head + (body << 2) + (lane - 24);
        atomicAdd(out + base_g + tap, tapval(tap, frac, amp, c, cw, sw));
    }
}

extern "C" void kernel_launch(void* const* d_in, const int* in_sizes, int n_in,
                              void* d_out, int out_size)
{
    const float* in = (const float*)d_in[0];
    float* out = (float*)d_out;
    int B = in_sizes[0] / 9;
    if (B > MAXB) B = MAXB;

    int nrec   = B * NVALID;
    int zeroN4 = B * (RIR_LEN / 4);              // float4 count (RIR_LEN % 4 == 0)
    prep_kernel<<<(zeroN4 + 255) / 256, 256>>>(in, out, B, zeroN4);

    int threadsB = nrec * 32;                     // one warp per record
    tap_kernel<<<(threadsB + 255) / 256, 256>>>(in, out, nrec);
}